// round 2
// baseline (speedup 1.0000x reference)
#include <cuda_runtime.h>

// Grad3D: out = |dx| + |dy| + |dz| with central differences, zero-padded.
// x shape (4, 1, 192, 224, 192) fp32, contiguous.

#define Nn 4
#define Dd 192
#define Hh 224
#define Ww 192
#define HW (Hh * Ww)          // 43008
#define DHW (Dd * HW)         // 8257536

#define BH 16                 // H rows per block tile
#define DCHUNK 24             // D planes per block
#define NROWS (BH + 2)        // tile rows incl. halo
#define ROWSTRIDE 196         // floats per smem row (784 B, 16B-aligned rows)
                              // layout: [0..2]=pad, [3]=zero (w=-1), [4..195]=data, [196]=zero (w=192)
#define THREADS 256
#define QPERROW (Ww / 4)      // 48 float4 per row

__global__ void __launch_bounds__(THREADS)
grad3d_kernel(const float* __restrict__ x, float* __restrict__ out)
{
    __shared__ float sm[3][NROWS * ROWSTRIDE];

    const int tid = threadIdx.x;
    const int h0  = blockIdx.x * BH;      // 0..208
    const int d0  = blockIdx.y * DCHUNK;  // 0..168
    const int n   = blockIdx.z;

    const float* __restrict__ xb = x   + (size_t)n * DHW;
    float*       __restrict__ ob = out + (size_t)n * DHW;

    // Initialize zero guard columns (w=-1 and w=W) once; loads never touch them.
    for (int i = tid; i < 3 * NROWS * 2; i += THREADS) {
        int b = i / (NROWS * 2);
        int j = i % (NROWS * 2);
        int r = j >> 1;
        sm[b][r * ROWSTRIDE + ((j & 1) ? (4 + Ww) : 3)] = 0.0f;
    }

    // Cooperative plane load: rows [h0-1, h0+BH] of plane p into buffer bsel.
    auto load_plane = [&](int p, int bsel) {
        const float* __restrict__ src = xb + (size_t)p * HW;
        float* __restrict__ dst = sm[bsel];
        for (int i = tid; i < NROWS * QPERROW; i += THREADS) {
            int r  = i / QPERROW;
            int q  = i % QPERROW;
            int gh = h0 - 1 + r;
            float4 v = make_float4(0.f, 0.f, 0.f, 0.f);
            if (gh >= 0 && gh < Hh)
                v = *reinterpret_cast<const float4*>(src + gh * Ww + q * 4);
            *reinterpret_cast<float4*>(dst + r * ROWSTRIDE + 4 + q * 4) = v;
        }
    };

    // Prologue: planes d0-1 (if any) and d0.
    if (d0 > 0) load_plane(d0 - 1, (d0 - 1) % 3);
    load_plane(d0, d0 % 3);

    for (int d = d0; d < d0 + DCHUNK; ++d) {
        if (d + 1 < Dd) load_plane(d + 1, (d + 1) % 3);
        __syncthreads();

        const float* __restrict__ cur = sm[d % 3];
        const float* __restrict__ pv  = sm[((d - 1) % 3 + 3) % 3];
        const float* __restrict__ nx  = sm[(d + 1) % 3];
        const bool hasP = (d > 0);
        const bool hasN = (d + 1 < Dd);

        float* __restrict__ orow = ob + (size_t)d * HW;

#pragma unroll
        for (int k = 0; k < 3; ++k) {
            int q  = tid + k * THREADS;       // 0..767 (16 rows x 48 quads)
            int r  = q / QPERROW;
            int w4 = (q % QPERROW) * 4;

            const float* c = cur + (r + 1) * ROWSTRIDE + 4 + w4;
            float4 cc = *reinterpret_cast<const float4*>(c);
            float  lf = c[-1];
            float  rt = c[4];
            float4 up = *reinterpret_cast<const float4*>(cur + r       * ROWSTRIDE + 4 + w4);
            float4 dn = *reinterpret_cast<const float4*>(cur + (r + 2) * ROWSTRIDE + 4 + w4);
            float4 pp = hasP ? *reinterpret_cast<const float4*>(pv + (r + 1) * ROWSTRIDE + 4 + w4)
                             : make_float4(0.f, 0.f, 0.f, 0.f);
            float4 nn = hasN ? *reinterpret_cast<const float4*>(nx + (r + 1) * ROWSTRIDE + 4 + w4)
                             : make_float4(0.f, 0.f, 0.f, 0.f);

            float4 o;
            o.x = 0.5f * (fabsf(cc.y - lf)   + fabsf(dn.x - up.x) + fabsf(nn.x - pp.x));
            o.y = 0.5f * (fabsf(cc.z - cc.x) + fabsf(dn.y - up.y) + fabsf(nn.y - pp.y));
            o.z = 0.5f * (fabsf(cc.w - cc.y) + fabsf(dn.z - up.z) + fabsf(nn.z - pp.z));
            o.w = 0.5f * (fabsf(rt   - cc.z) + fabsf(dn.w - up.w) + fabsf(nn.w - pp.w));

            *reinterpret_cast<float4*>(orow + (h0 + r) * Ww + w4) = o;
        }
        __syncthreads();  // protect pv buffer before it is overwritten next iter
    }
}

extern "C" void kernel_launch(void* const* d_in, const int* in_sizes, int n_in,
                              void* d_out, int out_size)
{
    const float* x = (const float*)d_in[0];
    float* out = (float*)d_out;
    dim3 grid(Hh / BH, Dd / DCHUNK, Nn);  // 14 x 8 x 4 = 448 blocks
    grad3d_kernel<<<grid, THREADS>>>(x, out);
}

// round 4
// speedup vs baseline: 1.5754x; 1.5754x over previous
#include <cuda_runtime.h>
#include <cuda_pipeline_primitives.h>

// Grad3D: out = |dx| + |dy| + |dz| with central differences, zero-padded.
// x shape (4, 1, 192, 224, 192) fp32, contiguous.

#define Nn 4
#define Dd 192
#define Hh 224
#define Ww 192
#define HW (Hh * Ww)          // 43008
#define DHW (Dd * HW)         // 8257536

#define BH 8                  // H rows per block tile
#define DCHUNK 16             // D planes per block
#define NROWS (BH + 2)        // tile rows incl. halo (10)
#define ROWSTRIDE 200         // floats per smem row (800 B, 16B-aligned):
                              // [3]=zero(w=-1), [4..195]=data, [196]=zero(w=192), [197..199]=pad
#define NBUF 4                // depth-2 async pipeline over D
#define THREADS 256
#define QPERROW (Ww / 4)      // 48 float4 per row
#define LOADQ (NROWS * QPERROW)   // 480 float4 per plane
#define COMPQ (BH * QPERROW)      // 384 output quads per plane

__global__ void __launch_bounds__(THREADS)
grad3d_kernel(const float* __restrict__ x, float* __restrict__ out)
{
    __shared__ __align__(16) float sm[NBUF][NROWS * ROWSTRIDE];

    const int tid = threadIdx.x;
    const int h0  = blockIdx.x * BH;      // 0..216
    const int d0  = blockIdx.y * DCHUNK;  // 0..176
    const int n   = blockIdx.z;

    const float* __restrict__ xb = x   + (size_t)n * DHW;
    float*       __restrict__ ob = out + (size_t)n * DHW;

    // Zero guard columns (w=-1 at [3], w=W at [196]) in every buffer row.
    for (int i = tid; i < NBUF * NROWS * 2; i += THREADS) {
        int b = i / (NROWS * 2);
        int j = i % (NROWS * 2);
        int r = j >> 1;
        sm[b][r * ROWSTRIDE + ((j & 1) ? (4 + Ww) : 3)] = 0.0f;
    }

    // Async plane load: rows [h0-1, h0+BH] of plane p into buffer p & 3.
    auto load_plane = [&](int p) {
        const float* __restrict__ src = xb + (size_t)p * HW;
        float* __restrict__ dst = sm[p & (NBUF - 1)];
        for (int i = tid; i < LOADQ; i += THREADS) {
            int r  = i / QPERROW;
            int q  = i - r * QPERROW;
            int gh = h0 - 1 + r;
            float* d4 = dst + r * ROWSTRIDE + 4 + q * 4;
            if (gh >= 0 && gh < Hh)
                __pipeline_memcpy_async(d4, src + gh * Ww + q * 4, 16);
            else
                *reinterpret_cast<float4*>(d4) = make_float4(0.f, 0.f, 0.f, 0.f);
        }
    };

    // Prologue: planes d0-1 (if any), d0, d0+1 (always exists since d0+1 <= 177).
    if (d0 > 0) { load_plane(d0 - 1); __pipeline_commit(); }
    load_plane(d0);     __pipeline_commit();
    load_plane(d0 + 1); __pipeline_commit();

    for (int d = d0; d < d0 + DCHUNK; ++d) {
        const int pnext = d + 2;
        const bool issue = (pnext <= d0 + DCHUNK) && (pnext < Dd);
        if (issue) {
            load_plane(pnext);
            __pipeline_commit();
            __pipeline_wait_prior(1);   // plane d+1 (and older) complete
        } else {
            __pipeline_wait_prior(0);
        }
        __syncthreads();

        const float* __restrict__ cur = sm[d & (NBUF - 1)];
        const float* __restrict__ pv  = sm[(d - 1) & (NBUF - 1)];
        const float* __restrict__ nx  = sm[(d + 1) & (NBUF - 1)];
        const bool hasP = (d > 0);
        const bool hasN = (d + 1 < Dd);

        float* __restrict__ orow = ob + (size_t)d * HW;

        for (int i = tid; i < COMPQ; i += THREADS) {
            int r  = i / QPERROW;
            int w4 = (i - r * QPERROW) * 4;

            const float* c = cur + (r + 1) * ROWSTRIDE + 4 + w4;
            float4 cc = *reinterpret_cast<const float4*>(c);
            float  lf = c[-1];   // w4==0   -> left guard at [3]
            float  rt = c[4];    // w4==188 -> right guard at [196]
            float4 up = *reinterpret_cast<const float4*>(cur + r       * ROWSTRIDE + 4 + w4);
            float4 dn = *reinterpret_cast<const float4*>(cur + (r + 2) * ROWSTRIDE + 4 + w4);
            float4 pp = hasP ? *reinterpret_cast<const float4*>(pv + (r + 1) * ROWSTRIDE + 4 + w4)
                             : make_float4(0.f, 0.f, 0.f, 0.f);
            float4 nn = hasN ? *reinterpret_cast<const float4*>(nx + (r + 1) * ROWSTRIDE + 4 + w4)
                             : make_float4(0.f, 0.f, 0.f, 0.f);

            float4 o;
            o.x = 0.5f * (fabsf(cc.y - lf)   + fabsf(dn.x - up.x) + fabsf(nn.x - pp.x));
            o.y = 0.5f * (fabsf(cc.z - cc.x) + fabsf(dn.y - up.y) + fabsf(nn.y - pp.y));
            o.z = 0.5f * (fabsf(cc.w - cc.y) + fabsf(dn.z - up.z) + fabsf(nn.z - pp.z));
            o.w = 0.5f * (fabsf(rt   - cc.z) + fabsf(dn.w - up.w) + fabsf(nn.w - pp.w));

            *reinterpret_cast<float4*>(orow + (h0 + r) * Ww + w4) = o;
        }
        __syncthreads();  // all reads of buffer (d-1)&3 done before next iter's cp.async overwrites it
    }
}

extern "C" void kernel_launch(void* const* d_in, const int* in_sizes, int n_in,
                              void* d_out, int out_size)
{
    const float* x = (const float*)d_in[0];
    float* out = (float*)d_out;
    dim3 grid(Hh / BH, Dd / DCHUNK, Nn);  // 28 x 12 x 4 = 1344 blocks
    grad3d_kernel<<<grid, THREADS>>>(x, out);
}

// round 6
// speedup vs baseline: 1.7591x; 1.1166x over previous
#include <cuda_runtime.h>

// Grad3D: out = |dx| + |dy| + |dz| with central differences, zero-padded.
// x shape (4, 1, 192, 224, 192) fp32, contiguous.
// Register D-march: each thread owns one (h, w4) quad, marches DCHUNK planes.
// z-derivative and center value live in registers; smem holds only the current
// plane (double-buffered) for lf/rt/up/dn neighbor reads.

#define Nn 4
#define Dd 192
#define Hh 224
#define Ww 192
#define HW (Hh * Ww)          // 43008
#define DHW (Dd * HW)         // 8257536

#define BH 8                  // H output rows per block
#define DCHUNK 16             // D planes per block
#define NROWS (BH + 2)        // incl. halo rows (10)
#define ROWSTRIDE 200         // floats/row (800B): [3]=zero(w=-1), [4..195]=data, [196]=zero(w=192)
#define QPERROW (Ww / 4)      // 48
#define THREADS (NROWS * QPERROW)  // 480

__global__ void __launch_bounds__(THREADS, 3)
grad3d_kernel(const float* __restrict__ x, float* __restrict__ out)
{
    __shared__ __align__(16) float sm[2][NROWS * ROWSTRIDE];

    const int tid  = threadIdx.x;
    const int r    = tid / QPERROW;       // 0..9 (r=0, r=9 are halo rows)
    const int q    = tid - r * QPERROW;   // 0..47
    const int h0   = blockIdx.x * BH;     // 0..216
    const int d0   = blockIdx.y * DCHUNK; // 0..176
    const int dend = d0 + DCHUNK;
    const int n    = blockIdx.z;
    const int gh   = h0 - 1 + r;
    const bool inH  = (gh >= 0) && (gh < Hh);
    const bool comp = (r >= 1) && (r <= BH);

    // Zero guard columns (w=-1 at [3], w=W at [196]) in both buffers.
    if (q == 0) {
        sm[0][r * ROWSTRIDE + 3] = 0.0f;
        sm[0][r * ROWSTRIDE + 4 + Ww] = 0.0f;
        sm[1][r * ROWSTRIDE + 3] = 0.0f;
        sm[1][r * ROWSTRIDE + 4 + Ww] = 0.0f;
    }

    const float* __restrict__ src =
        x + (size_t)n * DHW + (size_t)(inH ? gh : 0) * Ww + q * 4;
    float* __restrict__ dst =
        out + (size_t)n * DHW + (size_t)(comp ? (gh) : 0) * Ww + q * 4;

    const int soff = r * ROWSTRIDE + 4 + q * 4;

    auto ldq = [&](int d) -> float4 {
        if (inH && (unsigned)d < (unsigned)Dd)
            return *reinterpret_cast<const float4*>(src + (size_t)d * HW);
        return make_float4(0.f, 0.f, 0.f, 0.f);
    };

    // Invariant entering iter d: regs r_prev=x[d-1], r_cur=x[d], r_next=x[d+1];
    // sm[d&1] holds plane d.
    float4 r_prev = ldq(d0 - 1);
    float4 r_cur  = ldq(d0);
    float4 r_next = ldq(d0 + 1);
    *reinterpret_cast<float4*>(&sm[d0 & 1][soff]) = r_cur;
    __syncthreads();

    for (int d = d0; d < dend; ++d) {
        // Prefetch plane d+2 (becomes r_next after rotation; last useful load is d+2==dend).
        float4 tmp = (d + 2 <= dend) ? ldq(d + 2)
                                     : make_float4(0.f, 0.f, 0.f, 0.f);

        // Publish plane d+1 for next iteration's neighbor reads.
        if (d + 1 < dend)
            *reinterpret_cast<float4*>(&sm[(d + 1) & 1][soff]) = r_next;

        if (comp) {
            const float* cb = &sm[d & 1][soff];
            float  lf = cb[-1];                                          // guard at q==0
            float  rt = cb[4];                                           // guard at q==47
            float4 up = *reinterpret_cast<const float4*>(cb - ROWSTRIDE);
            float4 dn = *reinterpret_cast<const float4*>(cb + ROWSTRIDE);

            float4 o;
            o.x = 0.5f * (fabsf(r_cur.y - lf)      + fabsf(dn.x - up.x) + fabsf(r_next.x - r_prev.x));
            o.y = 0.5f * (fabsf(r_cur.z - r_cur.x) + fabsf(dn.y - up.y) + fabsf(r_next.y - r_prev.y));
            o.z = 0.5f * (fabsf(r_cur.w - r_cur.y) + fabsf(dn.z - up.z) + fabsf(r_next.z - r_prev.z));
            o.w = 0.5f * (fabsf(rt     - r_cur.z)  + fabsf(dn.w - up.w) + fabsf(r_next.w - r_prev.w));

            *reinterpret_cast<float4*>(dst + (size_t)d * HW) = o;
        }

        __syncthreads();   // sm[(d+1)&1] published; reads of sm[d&1] complete
        r_prev = r_cur; r_cur = r_next; r_next = tmp;
    }
}

extern "C" void kernel_launch(void* const* d_in, const int* in_sizes, int n_in,
                              void* d_out, int out_size)
{
    const float* x = (const float*)d_in[0];
    float* out = (float*)d_out;
    dim3 grid(Hh / BH, Dd / DCHUNK, Nn);   // 28 x 12 x 4 = 1344 blocks
    grad3d_kernel<<<grid, THREADS>>>(x, out);
}